// round 8
// baseline (speedup 1.0000x reference)
#include <cuda_runtime.h>
#include <cuda_fp16.h>
#include <mma.h>
#include <cstdint>

using namespace nvcuda;

// ---------------------------------------------------------------------------
// S4D kernel materialization via WMMA fp16 tensor cores (HMMA, sm_100-safe).
//   K[d,l] = 2*Re( sum_n Cc[d,n] * exp(dtA[d,n] * l) ),  D=512, N=32, L=8192
//
// Split l = 64*m + b (m in [0,128), b in [0,64)):
//   K[d, 64m+b] = sum_k A[m,k] * B[b,k]       (real GEMM, Kdim = 64)
//   A[m, n]    = Re(u),  A[m, 32+n] = Im(u),  u = 2*Cc_n * exp(dtA_n*64m)
//   B[b, n]    = Re(w),  B[b, 32+n] = -Im(w), w = exp(dtA_n*b)
//
// Round 8: single-pass fp16 (A and B both fp16; measured error budget
// ~2.7e-4 vs 1e-3 gate), chain-free direct-exp tables built by all 4 warps
// in parallel (fp64 angle product -> exact phase), 2 syncthreads total.
// ---------------------------------------------------------------------------

#define D_MODEL 512
#define SEQ     8192
#define NST     32
#define LDAB    72                    // fp16 elems per A/B smem row (144 B)

// Dynamic smem layout (bytes)
#define OFF_AH  0                     // 128 x 144 = 18432
#define OFF_BH  18432                 // 64 x 144  = 9216
#define OFF_TR  27648                 // float2[16][34] = 4352  (R tables)
#define OFF_TQ  32000                 // float2[24][34] = 6528  (Q tables)
#define TROW    34
#define SMEM_TOTAL 38528

// ---- helpers ---------------------------------------------------------------
__device__ __forceinline__ float2 cmul(float2 a, float2 b) {
    return make_float2(a.x * b.x - a.y * b.y, a.x * b.y + a.y * b.x);
}
// exp(scale*(dtAr + i*dtAi)), scale integer-valued up to 7680.
// Angle computed in fp64 then reduced mod 2pi -> exact phase, fp32 sin/cos.
__device__ __forceinline__ float2 cexp_int(float dtAr, float dtAi, float scale) {
    float e = __expf(scale * dtAr);
    double mi = (double)scale * (double)dtAi;
    double k  = rint(mi * 0.15915494309189535);
    float th  = (float)(mi - k * 6.283185307179586);
    float s, c;
    __sincosf(th, &s, &c);
    return make_float2(e * c, e * s);
}
// pack two fp32 -> half2 (v0 in low half = lower address)
__device__ __forceinline__ uint32_t pkh2(float v0, float v1) {
    __half2 h = __halves2half2(__float2half_rn(v0), __float2half_rn(v1));
    return *(uint32_t*)&h;
}

// ---------------------------------------------------------------------------
__global__ void __launch_bounds__(128, 4)
s4d_wmma_kernel(const float* __restrict__ log_dt,
                const float* __restrict__ log_A_real,
                const float* __restrict__ A_imag,
                const float2* __restrict__ C,
                float* __restrict__ out)
{
    extern __shared__ char dsm[];
    float2*   tR   = (float2*)(dsm + OFF_TR);   // rows 0-7: r^i ; 8-15: r^(8j)
    float2*   tQ   = (float2*)(dsm + OFF_TQ);   // rows 0-7: r^(64i); 8-23: Cc*r^(512j)
    uint32_t* ah32 = (uint32_t*)(dsm + OFF_AH); // 36 u32 per row
    uint32_t* bh32 = (uint32_t*)(dsm + OFF_BH);

    const int d    = blockIdx.x;
    const int tid  = threadIdx.x;
    const int wid  = tid >> 5;
    const int lane = tid & 31;

    // ---- Phase 1: all tables, direct exponentials, 10 rows per warp --------
    {
        int i = d * NST + lane;
        float dt   = __expf(log_dt[d]);
        float Ar   = -expf(log_A_real[i]);
        float Ai   = A_imag[i];
        float dtAr = Ar * dt;
        float dtAi = Ai * dt;

        // discretized C with the final 2x folded in (precise path, as R1-R7)
        float er = expf(dtAr);
        float s, c;
        sincosf(dtAi, &s, &c);
        float Er = er * c - 1.0f, Ei = er * s;
        float ar8 = Ar + 1e-8f;
        float inv = 1.0f / (ar8 * ar8 + Ai * Ai);
        float qr = (Er * ar8 + Ei * Ai) * inv;
        float qi = (Ei * ar8 - Er * Ai) * inv;
        float2 Cv = C[i];
        float2 Cc = make_float2(2.0f * (Cv.x * qr - Cv.y * qi),
                                2.0f * (Cv.x * qi + Cv.y * qr));

        // 40 logical rows: [0,8) R1=r^i ; [8,16) R2=r^(8j) ;
        //                  [16,24) Q1=r^(64i) ; [24,40) Q2=Cc*r^(512j)
#pragma unroll
        for (int rr = 0; rr < 10; rr++) {
            int rho = wid * 10 + rr;
            float scale;
            if      (rho < 8)  scale = (float)rho;
            else if (rho < 16) scale = (float)(8 * (rho - 8));
            else if (rho < 24) scale = (float)(64 * (rho - 16));
            else               scale = (float)(512 * (rho - 24));
            float2 v = cexp_int(dtAr, dtAi, scale);
            if (rho >= 24) v = cmul(Cc, v);
            if (rho < 16) tR[rho * TROW + lane] = v;
            else          tQ[(rho - 16) * TROW + lane] = v;
        }
    }
    __syncthreads();

    // ---- Phase 2: operands (merged). Each thread: A row tid + half B row ---
    {
        // A row m = tid: u = Q1[m&7] * Q2[m>>3]
        int m = tid;
        const float4* ra = (const float4*)(tQ + (m & 7) * TROW);
        const float4* rb = (const float4*)(tQ + (8 + (m >> 3)) * TROW);
#pragma unroll
        for (int n2 = 0; n2 < 16; n2++) {
            float4 a = ra[n2], q = rb[n2];
            float2 u0 = cmul(make_float2(a.x, a.y), make_float2(q.x, q.y));
            float2 u1 = cmul(make_float2(a.z, a.w), make_float2(q.z, q.w));
            ah32[m * 36 + n2]      = pkh2(u0.x, u1.x);   // Re
            ah32[m * 36 + 16 + n2] = pkh2(u0.y, u1.y);   // Im
        }

        // Half B row: b = tid>>1, n2 in [8*(tid&1), +8): w = R1[b&7]*R2[b>>3]
        int b  = tid >> 1;
        int h0 = (tid & 1) * 8;
        const float4* sa = (const float4*)(tR + (b & 7) * TROW);
        const float4* sb = (const float4*)(tR + (8 + (b >> 3)) * TROW);
#pragma unroll
        for (int n2i = 0; n2i < 8; n2i++) {
            int n2 = h0 + n2i;
            float4 a = sa[n2], q = sb[n2];
            float2 w0 = cmul(make_float2(a.x, a.y), make_float2(q.x, q.y));
            float2 w1 = cmul(make_float2(a.z, a.w), make_float2(q.z, q.w));
            bh32[b * 36 + n2]      = pkh2(w0.x, w1.x);    // Re
            bh32[b * 36 + 16 + n2] = pkh2(-w0.y, -w1.y);  // -Im
        }
    }
    __syncthreads();

    // ---- Phase 3: WMMA single pass. Warp w: M-tiles {2w,2w+1} x N 0..3 ------
    {
        const __half* Ah = (const __half*)(dsm + OFF_AH);
        const __half* Bh = (const __half*)(dsm + OFF_BH);

        wmma::fragment<wmma::accumulator, 16, 16, 16, float> acc[2][4];
#pragma unroll
        for (int i = 0; i < 2; i++)
#pragma unroll
            for (int j = 0; j < 4; j++) wmma::fill_fragment(acc[i][j], 0.0f);

#pragma unroll
        for (int k = 0; k < 4; k++) {
            wmma::fragment<wmma::matrix_a, 16, 16, 16, __half,
                           wmma::row_major> af[2];
#pragma unroll
            for (int i = 0; i < 2; i++)
                wmma::load_matrix_sync(
                    af[i], Ah + (wid * 2 + i) * 16 * LDAB + k * 16, LDAB);
#pragma unroll
            for (int j = 0; j < 4; j++) {
                wmma::fragment<wmma::matrix_b, 16, 16, 16, __half,
                               wmma::col_major> bf;
                wmma::load_matrix_sync(bf, Bh + j * 16 * LDAB + k * 16, LDAB);
                wmma::mma_sync(acc[0][j], af[0], bf, acc[0][j]);
                wmma::mma_sync(acc[1][j], af[1], bf, acc[1][j]);
            }
        }

        // ---- epilogue: D[m,b] -> out[d*8192 + m*64 + b] --------------------
        float* od = out + (size_t)d * SEQ;
#pragma unroll
        for (int i = 0; i < 2; i++)
#pragma unroll
            for (int j = 0; j < 4; j++)
                wmma::store_matrix_sync(
                    od + (wid * 2 + i) * 16 * 64 + j * 16, acc[i][j], 64,
                    wmma::mem_row_major);
    }
}

// ---------------------------------------------------------------------------
extern "C" void kernel_launch(void* const* d_in, const int* in_sizes, int n_in,
                              void* d_out, int out_size)
{
    const float*  log_dt     = (const float*)d_in[0];
    const float*  log_A_real = (const float*)d_in[1];
    const float*  A_imag     = (const float*)d_in[2];
    const float2* C          = (const float2*)d_in[3];
    float* out = (float*)d_out;

    static bool attr_set = false;
    if (!attr_set) {
        cudaFuncSetAttribute(s4d_wmma_kernel,
                             cudaFuncAttributeMaxDynamicSharedMemorySize,
                             SMEM_TOTAL);
        attr_set = true;
    }
    s4d_wmma_kernel<<<D_MODEL, 128, SMEM_TOTAL>>>(
        log_dt, log_A_real, A_imag, C, out);
}